// round 15
// baseline (speedup 1.0000x reference)
#include <cuda_runtime.h>
#include <cstdint>
#include <math_constants.h>

#define BATCH 4096
#define VSZ   256
#define NU    129
#define SKIP  25
#define NEGINF (-CUDART_INF_F)
#define FULL  0xFFFFFFFFu

#define ROW_BYTES   516
#define GROUP_ROWS  4
#define GROUP_BYTES 2064                     // 516*4, 16B multiple
#define PAIR_BYTES  (2 * GROUP_BYTES)        // both chains' groups per slot
#define FIRST_ROW   24                       // 516*24 is 16B aligned
#define NGROUPS     58
#define NSLOTS      3
#define WPB         4                        // warps per block; 2 batches per warp

// Strictly monotone float -> uint32 key (order-preserving bijection) + inverse
static __device__ __forceinline__ unsigned fkey(float f) {
    unsigned u = __float_as_uint(f);
    return u ^ ((unsigned)((int)u >> 31) | 0x80000000u);
}
static __device__ __forceinline__ float fkey_inv(unsigned k) {
    unsigned m = (k & 0x80000000u) ? 0x80000000u : 0xFFFFFFFFu;
    return __uint_as_float(k ^ m);
}

static __device__ __forceinline__ uint32_t smem_u32(const void* p) {
    uint32_t a;
    asm("{ .reg .u64 t; cvta.to.shared.u64 t, %1; cvt.u32.u64 %0, t; }" : "=r"(a) : "l"(p));
    return a;
}
static __device__ __forceinline__ void mbar_init(uint32_t mbar, uint32_t cnt) {
    asm volatile("mbarrier.init.shared.b64 [%0], %1;" :: "r"(mbar), "r"(cnt) : "memory");
}
static __device__ __forceinline__ void mbar_expect_tx(uint32_t mbar, uint32_t bytes) {
    asm volatile("mbarrier.arrive.expect_tx.shared.b64 _, [%0], %1;"
                 :: "r"(mbar), "r"(bytes) : "memory");
}
static __device__ __forceinline__ void bulk_g2s(uint32_t dst, const void* src, uint32_t bytes, uint32_t mbar) {
    asm volatile("cp.async.bulk.shared::cta.global.mbarrier::complete_tx::bytes [%0], [%1], %2, [%3];"
                 :: "r"(dst), "l"(src), "r"(bytes), "r"(mbar) : "memory");
}
static __device__ __forceinline__ void mbar_wait(uint32_t mbar, uint32_t parity) {
    uint32_t done;
    asm volatile("{\n\t.reg .pred p;\n\t"
                 "mbarrier.try_wait.parity.acquire.cta.shared::cta.b64 p, [%1], %2;\n\t"
                 "selp.b32 %0, 1, 0, p;\n\t}"
                 : "=r"(done) : "r"(mbar), "r"(parity) : "memory");
    if (!done) {
        asm volatile("{\n\t.reg .pred P1;\n\t"
                     "W_%=:\n\t"
                     "mbarrier.try_wait.parity.acquire.cta.shared::cta.b64 P1, [%0], %1, 0x989680;\n\t"
                     "@P1 bra.uni D_%=;\n\t"
                     "bra.uni W_%=;\n\t"
                     "D_%=:\n\t}"
                     :: "r"(mbar), "r"(parity) : "memory");
    }
}

__global__ void __launch_bounds__(128, 4)
greedy_matching_kernel(const float* __restrict__ x, float* __restrict__ out) {
    // Per warp-slot: [chain A group | chain B group]
    __shared__ __align__(128) unsigned char sbuf[WPB][NSLOTS][2][GROUP_BYTES];
    __shared__ __align__(8)   unsigned long long smbar[WPB][NSLOTS];

    const int wib  = threadIdx.x >> 5;
    const int lane = threadIdx.x & 31;
    const int gw   = blockIdx.x * WPB + wib;   // 0..2047
    const int bA   = 2 * gw;                   // chain A batch
    const int bB   = 2 * gw + 1;               // chain B batch

    const float* __restrict__ baseA = x + (size_t)bA * (VSZ * NU);
    const float* __restrict__ baseB = x + (size_t)bB * (VSZ * NU);
    float* __restrict__ piA = out + BATCH + (size_t)bA * VSZ;
    float* __restrict__ piB = out + BATCH + (size_t)bB * VSZ;

    const uint32_t sb  = smem_u32(&sbuf[wib][0][0][0]);
    const uint32_t mbb = smem_u32(&smbar[wib][0]);

    // lane 0: init per-warp mbarriers, fence, prime the ring (groups 0..2, both chains)
    if (lane == 0) {
        mbar_init(mbb + 0, 1); mbar_init(mbb + 8, 1); mbar_init(mbb + 16, 1);
        asm volatile("fence.proxy.async.shared::cta;" ::: "memory");
#pragma unroll
        for (int s = 0; s < NSLOTS; ++s) {
            const size_t roff = (size_t)(FIRST_ROW + GROUP_ROWS * s) * NU;
            mbar_expect_tx(mbb + 8u * s, PAIR_BYTES);
            bulk_g2s(sb + s * PAIR_BYTES,               baseA + roff, GROUP_BYTES, mbb + 8u * s);
            bulk_g2s(sb + s * PAIR_BYTES + GROUP_BYTES, baseB + roff, GROUP_BYTES, mbb + 8u * s);
        }
    }
    __syncwarp();

    // Skip phase for both chains: sel = 0, weight 0, no mask change.
    if (lane <= 24) { piA[lane] = 0.0f; piB[lane] = 0.0f; }

    // R12 step state, duplicated per chain. STRIDED ownership: lane l owns
    // j = l, l+32, l+64, l+96; j = 128 real only on lane 0.
    float A0 = 0.f, A1 = 0.f, A2 = 0.f, A3 = 0.f;
    float B0 = 0.f, B1 = 0.f, B2 = 0.f, B3 = 0.f;
    float A4 = (lane == 0) ? 0.f : NEGINF;
    float B4 = (lane == 0) ? 0.f : NEGINF;
    const float z0 = (lane == 0) ? 0.f : 1.f;  // forces skip weight to 0 on lane 0
    const unsigned onebit = 1u << lane;
    float sizeA = 0.f, sizeB = 0.f;  // per-lane accumulators

    // Fused dual-chain step: two independent R12 steps, interleaved so the
    // two REDUX/ballot latencies overlap. rpA/rpB point at the two chains'
    // smem rows; emits piA[T], piB[T].
#define STEP2(rpA, rpB, T)                                                     \
    do {                                                                       \
        float a0 = (rpA)[lane];      float q0 = (rpB)[lane];                   \
        float a1 = (rpA)[lane + 32]; float q1 = (rpB)[lane + 32];              \
        float a2 = (rpA)[lane + 64]; float q2 = (rpB)[lane + 64];              \
        float a3 = (rpA)[lane + 96]; float q3 = (rpB)[lane + 96];              \
        float a4 = (rpA)[128];       float q4 = (rpB)[128];                    \
        float fa0 = fmaf(a0, z0, A0), fb0 = fmaf(q0, z0, B0);                  \
        float fa1 = a1 + A1,          fb1 = q1 + B1;                           \
        float fa2 = a2 + A2,          fb2 = q2 + B2;                           \
        float fa3 = a3 + A3,          fb3 = q3 + B3;                           \
        float fa4 = a4 + A4,          fb4 = q4 + B4;                           \
        float ma01 = fmaxf(fa0, fa1), mb01 = fmaxf(fb0, fb1);                  \
        float ma23 = fmaxf(fa2, fa3), mb23 = fmaxf(fb2, fb3);                  \
        float ma03 = fmaxf(ma01, ma23), mb03 = fmaxf(mb01, mb23);              \
        float lma  = fmaxf(ma03, fa4),  lmb  = fmaxf(mb03, fb4);               \
        int jaA = (fa1 > fa0) ? lane + 32 : lane;                              \
        int jaB = (fa3 > fa2) ? lane + 96 : lane + 64;                         \
        int jbA = (fb1 > fb0) ? lane + 32 : lane;                              \
        int jbB = (fb3 > fb2) ? lane + 96 : lane + 64;                         \
        int jloA = (ma23 > ma01) ? jaB : jaA;                                  \
        int jloB = (mb23 > mb01) ? jbB : jbA;                                  \
        int liA  = (fa4 > ma03) ? 128 : jloA;                                  \
        int liB  = (fb4 > mb03) ? 128 : jloB;                                  \
        unsigned mkA = fkey(lma), mkB = fkey(lmb);                             \
        unsigned gkA = __reduce_max_sync(FULL, mkA);                           \
        unsigned gkB = __reduce_max_sync(FULL, mkB);                           \
        unsigned eqA = __ballot_sync(FULL, mkA == gkA);                        \
        unsigned eqB = __ballot_sync(FULL, mkB == gkB);                        \
        /* ── chain A resolve (R12 structure, single-sided fast path) ── */    \
        if (__popc(eqA) == 1) {                                                \
            if (eqA == onebit) {                                               \
                sizeA += lma;                                                  \
                if (liA != 0) {                                                \
                    int tier = liA >> 5;                                       \
                    if (tier == 0) A0 = NEGINF;                                \
                    else if (tier == 1) A1 = NEGINF;                           \
                    else if (tier == 2) A2 = NEGINF;                           \
                    else if (tier == 3) A3 = NEGINF;                           \
                    else A4 = NEGINF;                                          \
                }                                                              \
                piA[T] = __int2float_rn(liA);                                  \
            }                                                                  \
        } else {                                                               \
            unsigned cand = (mkA == gkA) ? (unsigned)liA : FULL;               \
            int s = (int)__reduce_min_sync(FULL, cand);                        \
            int d = s - lane;                                                  \
            if (d == 0 && s != 0) A0 = NEGINF;                                 \
            if (d == 32)  A1 = NEGINF;                                         \
            if (d == 64)  A2 = NEGINF;                                         \
            if (d == 96)  A3 = NEGINF;                                         \
            if (d == 128) A4 = NEGINF;                                         \
            int owner = (s == 128) ? 0 : (s & 31);                             \
            if (lane == owner) sizeA += fkey_inv(gkA);                         \
            if (lane == 0) piA[T] = __int2float_rn(s);                         \
        }                                                                      \
        /* ── chain B resolve ── */                                            \
        if (__popc(eqB) == 1) {                                                \
            if (eqB == onebit) {                                               \
                sizeB += lmb;                                                  \
                if (liB != 0) {                                                \
                    int tier = liB >> 5;                                       \
                    if (tier == 0) B0 = NEGINF;                                \
                    else if (tier == 1) B1 = NEGINF;                           \
                    else if (tier == 2) B2 = NEGINF;                           \
                    else if (tier == 3) B3 = NEGINF;                           \
                    else B4 = NEGINF;                                          \
                }                                                              \
                piB[T] = __int2float_rn(liB);                                  \
            }                                                                  \
        } else {                                                               \
            unsigned cand = (mkB == gkB) ? (unsigned)liB : FULL;               \
            int s = (int)__reduce_min_sync(FULL, cand);                        \
            int d = s - lane;                                                  \
            if (d == 0 && s != 0) B0 = NEGINF;                                 \
            if (d == 32)  B1 = NEGINF;                                         \
            if (d == 64)  B2 = NEGINF;                                         \
            if (d == 96)  B3 = NEGINF;                                         \
            if (d == 128) B4 = NEGINF;                                         \
            int owner = (s == 128) ? 0 : (s & 31);                             \
            if (lane == owner) sizeB += fkey_inv(gkB);                         \
            if (lane == 0) piB[T] = __int2float_rn(s);                         \
        }                                                                      \
    } while (0)

    int stage = 0, phase = 0;

    // Group 0 (rows 24..27): row 24 is in the skip phase, consume rows 1..3.
    {
        mbar_wait(mbb + 0, 0);
        const unsigned char* pa = &sbuf[wib][0][0][0];
        const unsigned char* pb = &sbuf[wib][0][1][0];
        STEP2((const float*)(pa + 1 * ROW_BYTES), (const float*)(pb + 1 * ROW_BYTES), 25);
        STEP2((const float*)(pa + 2 * ROW_BYTES), (const float*)(pb + 2 * ROW_BYTES), 26);
        STEP2((const float*)(pa + 3 * ROW_BYTES), (const float*)(pb + 3 * ROW_BYTES), 27);
        if (lane == 0) {  // refill slot 0 with group 3 (both chains)
            const size_t roff = (size_t)(FIRST_ROW + GROUP_ROWS * NSLOTS) * NU;
            mbar_expect_tx(mbb + 0, PAIR_BYTES);
            bulk_g2s(sb + 0,           baseA + roff, GROUP_BYTES, mbb + 0);
            bulk_g2s(sb + GROUP_BYTES, baseB + roff, GROUP_BYTES, mbb + 0);
        }
        stage = 1;
    }

    // Groups 1..57: 4 dual steps each; refill group g+3 while g+3 < 58.
    // Safe: the last STEP2's REDUX/ballot converges the warp after every
    // lane's LDS of this slot, so lane 0's refill cannot race.
#pragma unroll 1
    for (int g = 1; g < NGROUPS; ++g) {
        mbar_wait(mbb + 8u * stage, phase);
        const unsigned char* pa = &sbuf[wib][stage][0][0];
        const unsigned char* pb = &sbuf[wib][stage][1][0];
        const int t0 = FIRST_ROW + GROUP_ROWS * g;
        STEP2((const float*)(pa + 0 * ROW_BYTES), (const float*)(pb + 0 * ROW_BYTES), t0 + 0);
        STEP2((const float*)(pa + 1 * ROW_BYTES), (const float*)(pb + 1 * ROW_BYTES), t0 + 1);
        STEP2((const float*)(pa + 2 * ROW_BYTES), (const float*)(pb + 2 * ROW_BYTES), t0 + 2);
        STEP2((const float*)(pa + 3 * ROW_BYTES), (const float*)(pb + 3 * ROW_BYTES), t0 + 3);
        if (lane == 0 && g + NSLOTS < NGROUPS) {
            const size_t roff = (size_t)(t0 + GROUP_ROWS * NSLOTS) * NU;
            mbar_expect_tx(mbb + 8u * stage, PAIR_BYTES);
            bulk_g2s(sb + stage * PAIR_BYTES,               baseA + roff, GROUP_BYTES, mbb + 8u * stage);
            bulk_g2s(sb + stage * PAIR_BYTES + GROUP_BYTES, baseB + roff, GROUP_BYTES, mbb + 8u * stage);
        }
        if (++stage == NSLOTS) { stage = 0; phase ^= 1; }
    }

    // Butterfly-sum the per-lane size accumulators (deterministic order).
#pragma unroll
    for (int o = 16; o; o >>= 1) {
        sizeA += __shfl_xor_sync(FULL, sizeA, o);
        sizeB += __shfl_xor_sync(FULL, sizeB, o);
    }
    if (lane == 0) { out[bA] = -sizeA; out[bB] = -sizeB; }
}

extern "C" void kernel_launch(void* const* d_in, const int* in_sizes, int n_in,
                              void* d_out, int out_size) {
    const float* x = (const float*)d_in[0];
    float* out = (float*)d_out;
    // 2048 warps, 2 batches each: 512 blocks x 128 threads
    greedy_matching_kernel<<<BATCH / (2 * WPB), 128>>>(x, out);
}

// round 16
// speedup vs baseline: 1.2404x; 1.2404x over previous
#include <cuda_runtime.h>
#include <cstdint>
#include <math_constants.h>

#define BATCH 4096
#define VSZ   256
#define NU    129
#define SKIP  25
#define NEGINF (-CUDART_INF_F)
#define FULL  0xFFFFFFFFu

#define ROW_BYTES   516
#define GROUP_ROWS  4
#define GROUP_BYTES 2064                     // 516*4, 16B multiple
#define FIRST_ROW   24                       // 516*24 is 16B aligned
#define NGROUPS     58
#define NSLOTS      3
#define WPB         4

// Strictly monotone float -> uint32 key (order-preserving bijection) + inverse
static __device__ __forceinline__ unsigned fkey(float f) {
    unsigned u = __float_as_uint(f);
    return u ^ ((unsigned)((int)u >> 31) | 0x80000000u);
}
static __device__ __forceinline__ float fkey_inv(unsigned k) {
    unsigned m = (k & 0x80000000u) ? 0x80000000u : 0xFFFFFFFFu;
    return __uint_as_float(k ^ m);
}

static __device__ __forceinline__ uint32_t smem_u32(const void* p) {
    uint32_t a;
    asm("{ .reg .u64 t; cvta.to.shared.u64 t, %1; cvt.u32.u64 %0, t; }" : "=r"(a) : "l"(p));
    return a;
}
static __device__ __forceinline__ void mbar_init(uint32_t mbar, uint32_t cnt) {
    asm volatile("mbarrier.init.shared.b64 [%0], %1;" :: "r"(mbar), "r"(cnt) : "memory");
}
static __device__ __forceinline__ void mbar_expect_tx(uint32_t mbar, uint32_t bytes) {
    asm volatile("mbarrier.arrive.expect_tx.shared.b64 _, [%0], %1;"
                 :: "r"(mbar), "r"(bytes) : "memory");
}
static __device__ __forceinline__ void bulk_g2s(uint32_t dst, const void* src, uint32_t bytes, uint32_t mbar) {
    asm volatile("cp.async.bulk.shared::cta.global.mbarrier::complete_tx::bytes [%0], [%1], %2, [%3];"
                 :: "r"(dst), "l"(src), "r"(bytes), "r"(mbar) : "memory");
}
static __device__ __forceinline__ void mbar_wait(uint32_t mbar, uint32_t parity) {
    uint32_t done;
    asm volatile("{\n\t.reg .pred p;\n\t"
                 "mbarrier.try_wait.parity.acquire.cta.shared::cta.b64 p, [%1], %2;\n\t"
                 "selp.b32 %0, 1, 0, p;\n\t}"
                 : "=r"(done) : "r"(mbar), "r"(parity) : "memory");
    if (!done) {
        asm volatile("{\n\t.reg .pred P1;\n\t"
                     "W_%=:\n\t"
                     "mbarrier.try_wait.parity.acquire.cta.shared::cta.b64 P1, [%0], %1, 0x989680;\n\t"
                     "@P1 bra.uni D_%=;\n\t"
                     "bra.uni W_%=;\n\t"
                     "D_%=:\n\t}"
                     :: "r"(mbar), "r"(parity) : "memory");
    }
}

__global__ void __launch_bounds__(128, 7)
greedy_matching_kernel(const float* __restrict__ x, float* __restrict__ out) {
    __shared__ __align__(128) unsigned char sbuf[WPB][NSLOTS][GROUP_BYTES];
    __shared__ __align__(8)   unsigned long long smbar[WPB][NSLOTS];

    const int wib  = threadIdx.x >> 5;
    const int lane = threadIdx.x & 31;
    const int warp = blockIdx.x * WPB + wib;

    const float* __restrict__ base = x + (size_t)warp * (VSZ * NU);
    float* __restrict__ pi_out = out + BATCH + (size_t)warp * VSZ;

    const uint32_t sb  = smem_u32(&sbuf[wib][0][0]);
    const uint32_t mbb = smem_u32(&smbar[wib][0]);

    // lane 0: init per-warp mbarriers, fence, prime the 3-slot ring (groups 0..2)
    if (lane == 0) {
        mbar_init(mbb + 0, 1); mbar_init(mbb + 8, 1); mbar_init(mbb + 16, 1);
        asm volatile("fence.proxy.async.shared::cta;" ::: "memory");
#pragma unroll
        for (int s = 0; s < NSLOTS; ++s) {
            mbar_expect_tx(mbb + 8u * s, GROUP_BYTES);
            bulk_g2s(sb + s * GROUP_BYTES,
                     base + (size_t)(FIRST_ROW + GROUP_ROWS * s) * NU,
                     GROUP_BYTES, mbb + 8u * s);
        }
    }
    __syncwarp();

    // Skip phase: sel = 0, weight 0, no mask change.
    for (int t = lane; t < SKIP; t += 32) pi_out[t] = 0.0f;

    // STRIDED ownership: lane l owns j = l, l+32, l+64, l+96; j = 128 real
    // only on lane 0 (b4 = -inf elsewhere). Bias: 0 = available, -inf = matched.
    float b0 = 0.f, b1 = 0.f, b2 = 0.f, b3 = 0.f;
    float b4 = (lane == 0) ? 0.f : NEGINF;
    const float z0 = (lane == 0) ? 0.f : 1.f;  // forces skip weight to 0 on lane 0
    const unsigned onebit = 1u << lane;
    float size = 0.f;   // per-lane accumulator; butterfly-summed at the end

    // Two register banks A/B for the 2-deep software pipeline.
    float A0, A1, A2, A3, A4, B0, B1, B2, B3, B4;

#define LOADW(P, rp)                                                           \
    do {                                                                       \
        const float* _r = (const float*)(rp);                                  \
        P##0 = _r[lane];      P##1 = _r[lane + 32];                            \
        P##2 = _r[lane + 64]; P##3 = _r[lane + 96];                            \
        P##4 = _r[128];                                                        \
    } while (0)

    // R12 step on register bank P. PRE (a LOADW of the other bank, or
    // nothing) is issued right after P is consumed into f0..f4, so those
    // 5 LDS overlap the tree + REDUX + ballot + branch (~100 cyc) and the
    // next step sees its data already in registers.
#define STEP_CORE(P, T, PRE)                                                   \
    do {                                                                       \
        float f0 = fmaf(P##0, z0, b0);                                         \
        float f1 = P##1 + b1;                                                  \
        float f2 = P##2 + b2;                                                  \
        float f3 = P##3 + b3;                                                  \
        float f4 = P##4 + b4;                                                  \
        PRE;                                                                   \
        float m01 = fmaxf(f0, f1), m23 = fmaxf(f2, f3);                        \
        float m03 = fmaxf(m01, m23);                                           \
        float lm  = fmaxf(m03, f4);                                            \
        int jA = (f1 > f0)  ? lane + 32 : lane;                                \
        int jB = (f3 > f2)  ? lane + 96 : lane + 64;                           \
        int jlo = (m23 > m01) ? jB : jA;                                       \
        int li  = (f4 > m03) ? 128 : jlo;                                      \
        unsigned mk = fkey(lm);                                                \
        unsigned gk = __reduce_max_sync(FULL, mk);                             \
        unsigned eq = __ballot_sync(FULL, mk == gk);                           \
        if (__popc(eq) == 1) {                                                 \
            if (eq == onebit) {  /* unique winner lane does everything */      \
                size += lm;                                                    \
                if (li != 0) {                                                 \
                    int tier = li >> 5;                                        \
                    if (tier == 0) b0 = NEGINF;                                \
                    else if (tier == 1) b1 = NEGINF;                           \
                    else if (tier == 2) b2 = NEGINF;                           \
                    else if (tier == 3) b3 = NEGINF;                           \
                    else b4 = NEGINF;       /* li == 128, lane 0 */            \
                }                                                              \
                pi_out[T] = __int2float_rn(li);                                \
            }                                                                  \
        } else {  /* multi-lane key tie: exact first-index fallback */         \
            unsigned cand = (mk == gk) ? (unsigned)li : FULL;                  \
            int s = (int)__reduce_min_sync(FULL, cand);                        \
            int d = s - lane;                                                  \
            if (d == 0 && s != 0) b0 = NEGINF;                                 \
            if (d == 32)  b1 = NEGINF;                                         \
            if (d == 64)  b2 = NEGINF;                                         \
            if (d == 96)  b3 = NEGINF;                                         \
            if (d == 128) b4 = NEGINF;                                         \
            int owner = (s == 128) ? 0 : (s & 31);                             \
            if (lane == owner) size += fkey_inv(gk);                           \
            if (lane == 0) pi_out[T] = __int2float_rn(s);                      \
        }                                                                      \
    } while (0)

    int stage = 0, phase = 0;

    // Group 0 (rows 24..27): row 24 is in the skip phase, consume rows 1..3.
    {
        mbar_wait(mbb + 0, 0);
        const unsigned char* sp = &sbuf[wib][0][0];
        LOADW(A, sp + 1 * ROW_BYTES);
        STEP_CORE(A, 25, LOADW(B, sp + 2 * ROW_BYTES));
        STEP_CORE(B, 26, LOADW(A, sp + 3 * ROW_BYTES));
        STEP_CORE(A, 27, );
        if (lane == 0) {  // refill with group 3
            mbar_expect_tx(mbb + 0, GROUP_BYTES);
            bulk_g2s(sb + 0,
                     base + (size_t)(FIRST_ROW + GROUP_ROWS * NSLOTS) * NU,
                     GROUP_BYTES, mbb + 0);
        }
        stage = 1;
    }

    // Groups 1..57: 4 steps each; refill group g+3 while g+3 < 58.
    // Safe: the final STEP_CORE's REDUX/ballot converges the warp after every
    // lane has consumed its loaded values for this slot, so lane 0's refill
    // cannot race the reads.
#pragma unroll 1
    for (int g = 1; g < NGROUPS; ++g) {
        mbar_wait(mbb + 8u * stage, phase);
        const unsigned char* sp = &sbuf[wib][stage][0];
        const int t0 = FIRST_ROW + GROUP_ROWS * g;
        LOADW(A, sp + 0 * ROW_BYTES);                       // exposed once/group
        STEP_CORE(A, t0 + 0, LOADW(B, sp + 1 * ROW_BYTES));
        STEP_CORE(B, t0 + 1, LOADW(A, sp + 2 * ROW_BYTES));
        STEP_CORE(A, t0 + 2, LOADW(B, sp + 3 * ROW_BYTES));
        STEP_CORE(B, t0 + 3, );
        if (lane == 0 && g + NSLOTS < NGROUPS) {
            mbar_expect_tx(mbb + 8u * stage, GROUP_BYTES);
            bulk_g2s(sb + stage * GROUP_BYTES,
                     base + (size_t)(t0 + GROUP_ROWS * NSLOTS) * NU,
                     GROUP_BYTES, mbb + 8u * stage);
        }
        if (++stage == NSLOTS) { stage = 0; phase ^= 1; }
    }

    // Butterfly-sum the per-lane size accumulators (deterministic order).
#pragma unroll
    for (int o = 16; o; o >>= 1) size += __shfl_xor_sync(FULL, size, o);
    if (lane == 0) out[warp] = -size;
}

extern "C" void kernel_launch(void* const* d_in, const int* in_sizes, int n_in,
                              void* d_out, int out_size) {
    const float* x = (const float*)d_in[0];
    float* out = (float*)d_out;
    greedy_matching_kernel<<<BATCH / WPB, 128>>>(x, out);
}